// round 14
// baseline (speedup 1.0000x reference)
#include <cuda_runtime.h>
#include <cuda_bf16.h>
#include <math.h>

// Problem constants
#define BB 4
#define NN 20000
#define DD 64
#define KK 256
#define HH 4
#define DHD 16
#define FF 256
#define LLAYERS 2
#define NSPLIT 37
#define ATILES 157                   // 157*128 = 20096 >= 20000

// attn mma smem: sQ[128*72] + sP[128*72] + sC[2*64*72] + consts 192
#define ATTN_SMEM_WORDS (128 * 72 + 128 * 72 + 2 * 64 * 72 + 64 + 64 + 64)
#define ATTN_SMEM_BYTES (ATTN_SMEM_WORDS * 4)                         // 111360
// ffn mma smem: H[128][72]u + W1[64][72]u + W2[64][72]u + b1 256 + b2/g/be 192
#define FFN_SMEM_WORDS (128 * 72 + 64 * 72 + 64 * 72 + 256 + 64 + 64 + 64)
#define FFN_SMEM_BYTES (FFN_SMEM_WORDS * 4)                           // 75520

typedef unsigned long long u64;
typedef unsigned int u32;

// tf32 helpers
__device__ __forceinline__ u32 tf32c(float v) {
    u32 r; asm("cvt.rna.tf32.f32 %0,%1;" : "=r"(r) : "f"(v)); return r;
}
__device__ __forceinline__ void mma8(float4& c, u32 a0, u32 a1, u32 a2, u32 a3,
                                     u32 b0, u32 b1) {
    asm("mma.sync.aligned.m16n8k8.row.col.f32.tf32.tf32.f32 "
        "{%0,%1,%2,%3},{%4,%5,%6,%7},{%8,%9},{%0,%1,%2,%3};"
        : "+f"(c.x), "+f"(c.y), "+f"(c.z), "+f"(c.w)
        : "r"(a0), "r"(a1), "r"(a2), "r"(a3), "r"(b0), "r"(b1));
}

// Scratch (module-scope device arrays; no runtime allocation)
__device__ float g_x[BB * NN * DD];                 // activations  [B,N,D]
__device__ float g_part[NSPLIT * 2 * BB * KK * DD]; // split-N partials
__device__ float g_kvlow[2 * BB * KK * DD];         // reduced k_low / v_low
__device__ float g_kt[BB * DD * KK];                // k transposed  [b][d][k]
__device__ float g_v[BB * KK * DD];                 // v             [b][k][d]

// ---------------------------------------------------------------------------
// x[b,n,d] = emb[n,d] * expr[b,n]
__global__ void embed_kernel(const float* __restrict__ expr,
                             const float* __restrict__ emb) {
    int idx = blockIdx.x * blockDim.x + threadIdx.x;
    if (idx >= BB * NN) return;
    int b = idx / NN, n = idx % NN;
    float e = expr[b * NN + n];
    const float4* er = (const float4*)&emb[(size_t)n * DD];
    float4* xo = (float4*)&g_x[(size_t)idx * DD];
#pragma unroll
    for (int i = 0; i < DD / 4; i++) {
        float4 v = er[i];
        v.x *= e; v.y *= e; v.z *= e; v.w *= e;
        xo[i] = v;
    }
}

// ---------------------------------------------------------------------------
// Split-N low-rank projection with tf32 mma.sync, 32-row chunks.
__global__ __launch_bounds__(256) void proj_mma_kernel(const float* __restrict__ PK,
                                                       const float* __restrict__ PV) {
    __shared__ u32 sPu[32 * 264];
    __shared__ u32 sXu[32 * 72];
    int s = blockIdx.x, b = blockIdx.y, mat = blockIdx.z;
    const float* P = (mat == 0) ? PK : PV;
    int t = threadIdx.x;
    int w = t >> 5, L = t & 31, g = L >> 2, t4 = L & 3;

    float4 C[2][8];
#pragma unroll
    for (int i = 0; i < 2; i++)
#pragma unroll
        for (int j = 0; j < 8; j++) C[i][j] = make_float4(0.f, 0.f, 0.f, 0.f);

    int n0 = (s * NN) / NSPLIT;
    int n1 = ((s + 1) * NN) / NSPLIT;

    for (int n = n0; n < n1; n += 32) {
        __syncthreads();
#pragma unroll
        for (int j = 0; j < 8; j++) {
            int e = (t + j * 256) * 4;
            int row = e >> 8, col = e & 255;
            int nr = n + row;
            uint4 u;
            if (nr < n1) {
                float4 v = *(const float4*)&P[(size_t)nr * KK + col];
                u.x = tf32c(v.x); u.y = tf32c(v.y); u.z = tf32c(v.z); u.w = tf32c(v.w);
            } else u = make_uint4(0, 0, 0, 0);
            *(uint4*)&sPu[row * 264 + col] = u;
        }
#pragma unroll
        for (int j = 0; j < 2; j++) {
            int e = (t + j * 256) * 4;
            int row = e >> 6, col = e & 63;
            int nr = n + row;
            uint4 u;
            if (nr < n1) {
                float4 v = *(const float4*)&g_x[((size_t)b * NN + nr) * DD + col];
                u.x = tf32c(v.x); u.y = tf32c(v.y); u.z = tf32c(v.z); u.w = tf32c(v.w);
            } else u = make_uint4(0, 0, 0, 0);
            *(uint4*)&sXu[row * 72 + col] = u;
        }
        __syncthreads();

#pragma unroll
        for (int ks = 0; ks < 4; ks++) {
            int kr0 = (ks * 8 + t4) * 264;
            int kr1 = (ks * 8 + t4 + 4) * 264;
            u32 a[2][4];
#pragma unroll
            for (int mt = 0; mt < 2; mt++) {
                int m0 = w * 32 + mt * 16;
                a[mt][0] = sPu[kr0 + m0 + g];
                a[mt][1] = sPu[kr0 + m0 + g + 8];
                a[mt][2] = sPu[kr1 + m0 + g];
                a[mt][3] = sPu[kr1 + m0 + g + 8];
            }
            int xr0 = (ks * 8 + t4) * 72;
            int xr1 = (ks * 8 + t4 + 4) * 72;
#pragma unroll
            for (int nb = 0; nb < 8; nb++) {
                u32 b0 = sXu[xr0 + nb * 8 + g];
                u32 b1 = sXu[xr1 + nb * 8 + g];
                mma8(C[0][nb], a[0][0], a[0][1], a[0][2], a[0][3], b0, b1);
                mma8(C[1][nb], a[1][0], a[1][1], a[1][2], a[1][3], b0, b1);
            }
        }
    }

    float* o = g_part + (((size_t)s * 2 + mat) * BB + b) * (KK * DD);
#pragma unroll
    for (int mt = 0; mt < 2; mt++) {
        int m0 = w * 32 + mt * 16;
#pragma unroll
        for (int nb = 0; nb < 8; nb++) {
            int col = nb * 8 + 2 * t4;
            *(float2*)&o[(m0 + g) * DD + col] = make_float2(C[mt][nb].x, C[mt][nb].y);
            *(float2*)&o[(m0 + g + 8) * DD + col] = make_float2(C[mt][nb].z, C[mt][nb].w);
        }
    }
}

// ---------------------------------------------------------------------------
__global__ void reduce_kernel() {
    int idx = blockIdx.x * blockDim.x + threadIdx.x;
    if (idx >= 2 * BB * KK * DD) return;
    float sum = 0.f;
    for (int s = 0; s < NSPLIT; s++)
        sum += g_part[(size_t)s * (2 * BB * KK * DD) + idx];
    g_kvlow[idx] = sum;
}

// ---------------------------------------------------------------------------
// k/v head projections; K written transposed for the attention MMA.
__global__ void kvproj_kernel(const float* __restrict__ Wk,
                              const float* __restrict__ Wv) {
    int mat = blockIdx.z, b = blockIdx.y;
    const float* W = (mat == 0) ? Wk : Wv;
    __shared__ float sW[DD * DD];
    __shared__ float sL[4][DD];
    int t = threadIdx.x;
    for (int i = t * 4; i < DD * DD; i += 1024)
        *(float4*)&sW[i] = *(const float4*)&W[i];
    if (t < 64) {
        int r = t >> 4, c = (t & 15) * 4;
        int k = blockIdx.x * 4 + r;
        *(float4*)&sL[r][c] =
            *(const float4*)&g_kvlow[((size_t)mat * BB + b) * KK * DD + k * DD + c];
    }
    __syncthreads();
    int e = t & 63, kr = t >> 6;
    int k = blockIdx.x * 4 + kr;
    float sacc = 0.f;
#pragma unroll
    for (int d = 0; d < DD; d++) sacc += sL[kr][d] * sW[d * DD + e];
    if (mat == 0) {
        g_kt[((size_t)b * DD + e) * KK + k] = sacc;
    } else {
        g_v[(size_t)b * KK * DD + k * DD + e] = sacc;
    }
}

// ---------------------------------------------------------------------------
// Fused attention with tf32 mma.sync (R11 configuration, best so far).
__global__ __launch_bounds__(256, 2) void attn_mma_kernel(const float* __restrict__ Wq,
                                                          const float* __restrict__ Wo,
                                                          const float* __restrict__ bo,
                                                          const float* __restrict__ g1,
                                                          const float* __restrict__ be1) {
    extern __shared__ u32 smu[];
    u32* sQ = smu;                        // [128][72] tf32
    u32* sP = sQ + 128 * 72;              // [128][72] tf32 (P, later O)
    u32* sC = sP + 128 * 72;              // [2][64][72]: Wq | (KT,V) | Wo
    float* sBo = (float*)(sC + 2 * 64 * 72);
    float* sG = sBo + 64;
    float* sBe = sG + 64;

    int b = blockIdx.y, t = threadIdx.x;
    int w = t >> 5, L = t & 31, g = L >> 2, t4 = L & 3;
    int row0 = blockIdx.x * 128;
    int rg = row0 + w * 16 + g;
    int rg8 = rg + 8;
    bool vg = rg < NN, vg8 = rg8 < NN;
    const float* xbase = g_x + (size_t)b * NN * DD;
    int rq = w * 16 + g;

    if (t < 16) {
        *(float4*)&sBo[t * 4] = *(const float4*)&bo[t * 4];
        *(float4*)&sG[t * 4] = *(const float4*)&g1[t * 4];
        *(float4*)&sBe[t * 4] = *(const float4*)&be1[t * 4];
    }
#pragma unroll
    for (int j = 0; j < 4; j++) {
        int e = (t + j * 256) * 4;
        int r = e >> 6, c = e & 63;
        float4 v = *(const float4*)&Wq[r * DD + c];
        *(uint4*)&sC[r * 72 + c] =
            make_uint4(tf32c(v.x), tf32c(v.y), tf32c(v.z), tf32c(v.w));
    }
    __syncthreads();

    // Q = X @ Wq
    {
        float4 CQ[8];
#pragma unroll
        for (int nb = 0; nb < 8; nb++) CQ[nb] = make_float4(0.f, 0.f, 0.f, 0.f);
#pragma unroll
        for (int ks = 0; ks < 8; ks++) {
            u32 a0 = tf32c(vg ? xbase[(size_t)rg * DD + ks * 8 + t4] : 0.f);
            u32 a1 = tf32c(vg8 ? xbase[(size_t)rg8 * DD + ks * 8 + t4] : 0.f);
            u32 a2 = tf32c(vg ? xbase[(size_t)rg * DD + ks * 8 + t4 + 4] : 0.f);
            u32 a3 = tf32c(vg8 ? xbase[(size_t)rg8 * DD + ks * 8 + t4 + 4] : 0.f);
            int wr0 = (ks * 8 + t4) * 72;
            int wr1 = (ks * 8 + t4 + 4) * 72;
#pragma unroll
            for (int nb = 0; nb < 8; nb++) {
                u32 b0 = sC[wr0 + nb * 8 + g];
                u32 b1 = sC[wr1 + nb * 8 + g];
                mma8(CQ[nb], a0, a1, a2, a3, b0, b1);
            }
        }
#pragma unroll
        for (int nb = 0; nb < 8; nb++) {
            int col = nb * 8 + 2 * t4;
            *(uint2*)&sQ[rq * 72 + col] = make_uint2(tf32c(CQ[nb].x), tf32c(CQ[nb].y));
            *(uint2*)&sQ[(rq + 8) * 72 + col] =
                make_uint2(tf32c(CQ[nb].z), tf32c(CQ[nb].w));
        }
    }

    const float* ktb = g_kt + (size_t)b * DD * KK;   // [d][256]
    const float* vb = g_v + (size_t)b * KK * DD;     // [k][64]

    float lx[HH], lz[HH];
    float4 O[HH][2];
#pragma unroll
    for (int h = 0; h < HH; h++) {
        lx[h] = 0.f; lz[h] = 0.f;
        O[h][0] = make_float4(0.f, 0.f, 0.f, 0.f);
        O[h][1] = make_float4(0.f, 0.f, 0.f, 0.f);
    }

#pragma unroll 1
    for (int chunk = 0; chunk < 4; chunk++) {
        int k0 = chunk * 64;
        __syncthreads();
#pragma unroll
        for (int j = 0; j < 4; j++) {
            int e = (t + j * 256) * 4;
            int r = e >> 6, c = e & 63;
            float4 kv = *(const float4*)&ktb[(size_t)r * KK + k0 + c];
            *(uint4*)&sC[r * 72 + c] =
                make_uint4(tf32c(kv.x), tf32c(kv.y), tf32c(kv.z), tf32c(kv.w));
            float4 vv = *(const float4*)&vb[(size_t)(k0 + r) * DD + c];
            *(uint4*)&sC[64 * 72 + r * 72 + c] =
                make_uint4(tf32c(vv.x), tf32c(vv.y), tf32c(vv.z), tf32c(vv.w));
        }
        __syncthreads();

#pragma unroll
        for (int h = 0; h < HH; h++) {
            float4 CS[8];
#pragma unroll
            for (int nb = 0; nb < 8; nb++) CS[nb] = make_float4(0.f, 0.f, 0.f, 0.f);
#pragma unroll
            for (int ks = 0; ks < 2; ks++) {
                int kd = h * 16 + ks * 8;
                u32 a0 = sQ[rq * 72 + kd + t4];
                u32 a1 = sQ[(rq + 8) * 72 + kd + t4];
                u32 a2 = sQ[rq * 72 + kd + t4 + 4];
                u32 a3 = sQ[(rq + 8) * 72 + kd + t4 + 4];
                int wr0 = (kd + t4) * 72;
                int wr1 = (kd + t4 + 4) * 72;
#pragma unroll
                for (int nb = 0; nb < 8; nb++) {
                    u32 b0 = sC[wr0 + nb * 8 + g];
                    u32 b1 = sC[wr1 + nb * 8 + g];
                    mma8(CS[nb], a0, a1, a2, a3, b0, b1);
                }
            }
#pragma unroll
            for (int nb = 0; nb < 8; nb++) {
                float px = __expf(CS[nb].x * 0.25f);
                float py = __expf(CS[nb].y * 0.25f);
                float pz = __expf(CS[nb].z * 0.25f);
                float pw = __expf(CS[nb].w * 0.25f);
                lx[h] += px + py;
                lz[h] += pz + pw;
                int col = nb * 8 + 2 * t4;
                *(uint2*)&sP[rq * 72 + col] = make_uint2(tf32c(px), tf32c(py));
                *(uint2*)&sP[(rq + 8) * 72 + col] = make_uint2(tf32c(pz), tf32c(pw));
            }
            __syncwarp();
#pragma unroll
            for (int ks = 0; ks < 8; ks++) {
                u32 a0 = sP[rq * 72 + ks * 8 + t4];
                u32 a1 = sP[(rq + 8) * 72 + ks * 8 + t4];
                u32 a2 = sP[rq * 72 + ks * 8 + t4 + 4];
                u32 a3 = sP[(rq + 8) * 72 + ks * 8 + t4 + 4];
                int vr0 = 64 * 72 + (ks * 8 + t4) * 72;
                int vr1 = 64 * 72 + (ks * 8 + t4 + 4) * 72;
#pragma unroll
                for (int nb = 0; nb < 2; nb++) {
                    u32 b0 = sC[vr0 + h * 16 + nb * 8 + g];
                    u32 b1 = sC[vr1 + h * 16 + nb * 8 + g];
                    mma8(O[h][nb], a0, a1, a2, a3, b0, b1);
                }
            }
            __syncwarp();
        }
    }

#pragma unroll
    for (int h = 0; h < HH; h++) {
        lx[h] += __shfl_xor_sync(0xffffffffu, lx[h], 1);
        lx[h] += __shfl_xor_sync(0xffffffffu, lx[h], 2);
        lz[h] += __shfl_xor_sync(0xffffffffu, lz[h], 1);
        lz[h] += __shfl_xor_sync(0xffffffffu, lz[h], 2);
    }
#pragma unroll
    for (int h = 0; h < HH; h++) {
        float ix = 1.f / lx[h], iz = 1.f / lz[h];
#pragma unroll
        for (int nb = 0; nb < 2; nb++) {
            int col = h * 16 + nb * 8 + 2 * t4;
            *(uint2*)&sP[rq * 72 + col] =
                make_uint2(tf32c(O[h][nb].x * ix), tf32c(O[h][nb].y * ix));
            *(uint2*)&sP[(rq + 8) * 72 + col] =
                make_uint2(tf32c(O[h][nb].z * iz), tf32c(O[h][nb].w * iz));
        }
    }
    __syncthreads();
#pragma unroll
    for (int j = 0; j < 4; j++) {
        int e = (t + j * 256) * 4;
        int r = e >> 6, c = e & 63;
        float4 v = *(const float4*)&Wo[r * DD + c];
        *(uint4*)&sC[r * 72 + c] =
            make_uint4(tf32c(v.x), tf32c(v.y), tf32c(v.z), tf32c(v.w));
    }
    __syncthreads();

    float4 C2[8];
#pragma unroll
    for (int nb = 0; nb < 8; nb++) C2[nb] = make_float4(0.f, 0.f, 0.f, 0.f);
#pragma unroll
    for (int ks = 0; ks < 8; ks++) {
        u32 a0 = sP[rq * 72 + ks * 8 + t4];
        u32 a1 = sP[(rq + 8) * 72 + ks * 8 + t4];
        u32 a2 = sP[rq * 72 + ks * 8 + t4 + 4];
        u32 a3 = sP[(rq + 8) * 72 + ks * 8 + t4 + 4];
        int wr0 = (ks * 8 + t4) * 72;
        int wr1 = (ks * 8 + t4 + 4) * 72;
#pragma unroll
        for (int nb = 0; nb < 8; nb++) {
            u32 b0 = sC[wr0 + nb * 8 + g];
            u32 b1 = sC[wr1 + nb * 8 + g];
            mma8(C2[nb], a0, a1, a2, a3, b0, b1);
        }
    }

#pragma unroll 1
    for (int rp = 0; rp < 2; rp++) {
        int r = rp ? rg8 : rg;
        bool vr = rp ? vg8 : vg;
        float vx[8], vy[8];
#pragma unroll
        for (int nb = 0; nb < 8; nb++) {
            int col = nb * 8 + 2 * t4;
            float2 xv = vr ? *(const float2*)&xbase[(size_t)r * DD + col]
                           : make_float2(0.f, 0.f);
            float cva = rp ? C2[nb].z : C2[nb].x;
            float cvb = rp ? C2[nb].w : C2[nb].y;
            vx[nb] = cva + sBo[col] + xv.x;
            vy[nb] = cvb + sBo[col + 1] + xv.y;
        }
        float s = 0.f;
#pragma unroll
        for (int nb = 0; nb < 8; nb++) s += vx[nb] + vy[nb];
        s += __shfl_xor_sync(0xffffffffu, s, 1);
        s += __shfl_xor_sync(0xffffffffu, s, 2);
        float m = s * (1.f / DD);
        float q = 0.f;
#pragma unroll
        for (int nb = 0; nb < 8; nb++) {
            float d0 = vx[nb] - m, d1 = vy[nb] - m;
            q += d0 * d0 + d1 * d1;
        }
        q += __shfl_xor_sync(0xffffffffu, q, 1);
        q += __shfl_xor_sync(0xffffffffu, q, 2);
        float inv = rsqrtf(q * (1.f / DD) + 1e-5f);
        if (vr) {
            float* op = g_x + ((size_t)b * NN + r) * DD;
#pragma unroll
            for (int nb = 0; nb < 8; nb++) {
                int col = nb * 8 + 2 * t4;
                float2 o2;
                o2.x = (vx[nb] - m) * inv * sG[col] + sBe[col];
                o2.y = (vy[nb] - m) * inv * sG[col + 1] + sBe[col + 1];
                *(float2*)&op[col] = o2;
            }
        }
    }
}

// ---------------------------------------------------------------------------
// Fused FFN with tf32 mma.sync (R11 configuration).
__global__ __launch_bounds__(256, 2) void ffn_mma_kernel(const float* __restrict__ W1,
                                                         const float* __restrict__ b1,
                                                         const float* __restrict__ W2,
                                                         const float* __restrict__ b2,
                                                         const float* __restrict__ g2,
                                                         const float* __restrict__ be2,
                                                         float* __restrict__ xout) {
    extern __shared__ u32 smu[];
    u32* sHu = smu;
    u32* sW1u = sHu + 128 * 72;
    u32* sW2u = sW1u + 64 * 72;
    float* sB1 = (float*)(sW2u + 64 * 72);
    float* sB2 = sB1 + 256;
    float* sG = sB2 + 64;
    float* sBe = sG + 64;

    int b = blockIdx.y, t = threadIdx.x;
    int w = t >> 5, L = t & 31, g = L >> 2, t4 = L & 3;
    int row0 = blockIdx.x * 128;

    if (t < 64) *(float4*)&sB1[t * 4] = *(const float4*)&b1[t * 4];
    if (t < 16) {
        *(float4*)&sB2[t * 4] = *(const float4*)&b2[t * 4];
        *(float4*)&sG[t * 4] = *(const float4*)&g2[t * 4];
        *(float4*)&sBe[t * 4] = *(const float4*)&be2[t * 4];
    }

    const float* xbase = g_x + (size_t)b * NN * DD;
    int rg = row0 + w * 16 + g;
    int rg8 = rg + 8;
    bool vg = rg < NN, vg8 = rg8 < NN;

    float4 C2[8];
#pragma unroll
    for (int nb = 0; nb < 8; nb++) C2[nb] = make_float4(0.f, 0.f, 0.f, 0.f);

#pragma unroll 1
    for (int fc = 0; fc < 4; fc++) {
        int f0 = fc * 64;
        __syncthreads();
#pragma unroll
        for (int j = 0; j < 4; j++) {
            int e = (t + j * 256) * 4;
            int r = e >> 6, c = e & 63;
            float4 v1 = *(const float4*)&W1[r * FF + f0 + c];
            *(uint4*)&sW1u[r * 72 + c] =
                make_uint4(tf32c(v1.x), tf32c(v1.y), tf32c(v1.z), tf32c(v1.w));
            float4 v2 = *(const float4*)&W2[(f0 + r) * DD + c];
            *(uint4*)&sW2u[r * 72 + c] =
                make_uint4(tf32c(v2.x), tf32c(v2.y), tf32c(v2.z), tf32c(v2.w));
        }
        __syncthreads();

        float4 C1[8];
#pragma unroll
        for (int nb = 0; nb < 8; nb++) {
            int col = f0 + nb * 8 + 2 * t4;
            C1[nb] = make_float4(sB1[col], sB1[col + 1], sB1[col], sB1[col + 1]);
        }
#pragma unroll
        for (int ks = 0; ks < 8; ks++) {
            u32 a0 = tf32c(vg ? xbase[(size_t)rg * DD + ks * 8 + t4] : 0.f);
            u32 a1 = tf32c(vg8 ? xbase[(size_t)rg8 * DD + ks * 8 + t4] : 0.f);
            u32 a2 = tf32c(vg ? xbase[(size_t)rg * DD + ks * 8 + t4 + 4] : 0.f);
            u32 a3 = tf32c(vg8 ? xbase[(size_t)rg8 * DD + ks * 8 + t4 + 4] : 0.f);
            int wr0 = (ks * 8 + t4) * 72;
            int wr1 = (ks * 8 + t4 + 4) * 72;
#pragma unroll
            for (int nb = 0; nb < 8; nb++) {
                u32 b0 = sW1u[wr0 + nb * 8 + g];
                u32 b1r = sW1u[wr1 + nb * 8 + g];
                mma8(C1[nb], a0, a1, a2, a3, b0, b1r);
            }
        }
#pragma unroll
        for (int nb = 0; nb < 8; nb++) {
            float h0 = C1[nb].x, h1 = C1[nb].y, h2 = C1[nb].z, h3 = C1[nb].w;
            h0 = 0.5f * h0 * (1.f + erff(h0 * 0.70710678118654752440f));
            h1 = 0.5f * h1 * (1.f + erff(h1 * 0.70710678118654752440f));
            h2 = 0.5f * h2 * (1.f + erff(h2 * 0.70710678118654752440f));
            h3 = 0.5f * h3 * (1.f + erff(h3 * 0.70710678118654752440f));
            int col = nb * 8 + 2 * t4;
            *(uint2*)&sHu[(w * 16 + g) * 72 + col] = make_uint2(tf32c(h0), tf32c(h1));
            *(uint2*)&sHu[(w * 16 + g + 8) * 72 + col] = make_uint2(tf32c(h2), tf32c(h3));
        }
        __syncwarp();
#pragma unroll
        for (int ks = 0; ks < 8; ks++) {
            u32 a0 = sHu[(w * 16 + g) * 72 + ks * 8 + t4];
            u32 a1 = sHu[(w * 16 + g + 8) * 72 + ks * 8 + t4];
            u32 a2 = sHu[(w * 16 + g) * 72 + ks * 8 + t4 + 4];
            u32 a3 = sHu[(w * 16 + g + 8) * 72 + ks * 8 + t4 + 4];
            int wr0 = (ks * 8 + t4) * 72;
            int wr1 = (ks * 8 + t4 + 4) * 72;
#pragma unroll
            for (int nb = 0; nb < 8; nb++) {
                u32 b0 = sW2u[wr0 + nb * 8 + g];
                u32 b1r = sW2u[wr1 + nb * 8 + g];
                mma8(C2[nb], a0, a1, a2, a3, b0, b1r);
            }
        }
        __syncwarp();
    }

#pragma unroll 1
    for (int rp = 0; rp < 2; rp++) {
        int r = rp ? rg8 : rg;
        bool vr = rp ? vg8 : vg;
        float vx[8], vy[8];
#pragma unroll
        for (int nb = 0; nb < 8; nb++) {
            int col = nb * 8 + 2 * t4;
            float2 xv = vr ? *(const float2*)&xbase[(size_t)r * DD + col]
                           : make_float2(0.f, 0.f);
            float cva = rp ? C2[nb].z : C2[nb].x;
            float cvb = rp ? C2[nb].w : C2[nb].y;
            vx[nb] = cva + sB2[col] + xv.x;
            vy[nb] = cvb + sB2[col + 1] + xv.y;
        }
        float s = 0.f;
#pragma unroll
        for (int nb = 0; nb < 8; nb++) s += vx[nb] + vy[nb];
        s += __shfl_xor_sync(0xffffffffu, s, 1);
        s += __shfl_xor_sync(0xffffffffu, s, 2);
        float m = s * (1.f / DD);
        float q = 0.f;
#pragma unroll
        for (int nb = 0; nb < 8; nb++) {
            float d0 = vx[nb] - m, d1 = vy[nb] - m;
            q += d0 * d0 + d1 * d1;
        }
        q += __shfl_xor_sync(0xffffffffu, q, 1);
        q += __shfl_xor_sync(0xffffffffu, q, 2);
        float inv = rsqrtf(q * (1.f / DD) + 1e-5f);
        if (vr) {
            float* op = xout + ((size_t)b * NN + r) * DD;
#pragma unroll
            for (int nb = 0; nb < 8; nb++) {
                int col = nb * 8 + 2 * t4;
                float2 o2;
                o2.x = (vx[nb] - m) * inv * sG[col] + sBe[col];
                o2.y = (vy[nb] - m) * inv * sG[col + 1] + sBe[col + 1];
                *(float2*)&op[col] = o2;
            }
        }
    }
}

// ---------------------------------------------------------------------------
extern "C" void kernel_launch(void* const* d_in, const int* in_sizes, int n_in,
                              void* d_out, int out_size) {
    const float* expr = (const float*)d_in[0];
    const float* emb = (const float*)d_in[1];
    const float* Wq = (const float*)d_in[2];
    const float* Wk = (const float*)d_in[3];
    const float* Wv = (const float*)d_in[4];
    const float* projK = (const float*)d_in[5];
    const float* projV = (const float*)d_in[6];
    const float* Wo = (const float*)d_in[7];
    const float* bo = (const float*)d_in[8];
    const float* g1 = (const float*)d_in[9];
    const float* be1 = (const float*)d_in[10];
    const float* W1 = (const float*)d_in[11];
    const float* bf1 = (const float*)d_in[12];
    const float* W2 = (const float*)d_in[13];
    const float* bf2 = (const float*)d_in[14];
    const float* g2 = (const float*)d_in[15];
    const float* be2 = (const float*)d_in[16];
    float* out = (float*)d_out;

    void* xaddr = nullptr;
    cudaGetSymbolAddress(&xaddr, g_x);
    float* gx = (float*)xaddr;

    cudaFuncSetAttribute(attn_mma_kernel, cudaFuncAttributeMaxDynamicSharedMemorySize,
                         ATTN_SMEM_BYTES);
    cudaFuncSetAttribute(ffn_mma_kernel, cudaFuncAttributeMaxDynamicSharedMemorySize,
                         FFN_SMEM_BYTES);

    embed_kernel<<<(BB * NN + 255) / 256, 256>>>(expr, emb);

    for (int l = 0; l < LLAYERS; l++) {
        proj_mma_kernel<<<dim3(NSPLIT, BB, 2), 256>>>(projK + (size_t)l * NN * KK,
                                                      projV + (size_t)l * NN * KK);
        reduce_kernel<<<(2 * BB * KK * DD) / 256, 256>>>();
        kvproj_kernel<<<dim3(KK / 4, BB, 2), 256>>>(Wk + l * DD * DD,
                                                    Wv + l * DD * DD);
        attn_mma_kernel<<<dim3(ATILES, BB), 256, ATTN_SMEM_BYTES>>>(
            Wq + l * DD * DD, Wo + l * DD * DD, bo + l * DD, g1 + l * DD,
            be1 + l * DD);
        ffn_mma_kernel<<<dim3(ATILES, BB), 256, FFN_SMEM_BYTES>>>(
            W1 + (size_t)l * DD * FF, bf1 + l * FF, W2 + (size_t)l * FF * DD,
            bf2 + l * DD, g2 + l * DD, be2 + l * DD,
            (l == LLAYERS - 1) ? out : gx);
    }
}

// round 16
// speedup vs baseline: 1.3185x; 1.3185x over previous
#include <cuda_runtime.h>
#include <cuda_bf16.h>
#include <math.h>

// Problem constants
#define BB 4
#define NN 20000
#define DD 64
#define KK 256
#define HH 4
#define DHD 16
#define FF 256
#define LLAYERS 2
#define NSPLIT 37
#define ATILES 157                   // 157*128 = 20096 >= 20000

// attn mma smem: sQ[128*72] + sP[128*72] + sC[2*64*72] + consts 192
#define ATTN_SMEM_WORDS (128 * 72 + 128 * 72 + 2 * 64 * 72 + 64 + 64 + 64)
#define ATTN_SMEM_BYTES (ATTN_SMEM_WORDS * 4)                         // 111360
// ffn bf16 smem: sX[128*36] + sH[128*36] + sW1[32*72] + sW2[32*72] + b1/b2/g/be
#define FFN_SMEM_WORDS (128 * 36 + 128 * 36 + 32 * 72 + 32 * 72 + 256 + 64 + 64 + 64)
#define FFN_SMEM_BYTES (FFN_SMEM_WORDS * 4)                           // 57088

typedef unsigned long long u64;
typedef unsigned int u32;

// tf32 helpers
__device__ __forceinline__ u32 tf32c(float v) {
    u32 r; asm("cvt.rna.tf32.f32 %0,%1;" : "=r"(r) : "f"(v)); return r;
}
__device__ __forceinline__ void mma8(float4& c, u32 a0, u32 a1, u32 a2, u32 a3,
                                     u32 b0, u32 b1) {
    asm("mma.sync.aligned.m16n8k8.row.col.f32.tf32.tf32.f32 "
        "{%0,%1,%2,%3},{%4,%5,%6,%7},{%8,%9},{%0,%1,%2,%3};"
        : "+f"(c.x), "+f"(c.y), "+f"(c.z), "+f"(c.w)
        : "r"(a0), "r"(a1), "r"(a2), "r"(a3), "r"(b0), "r"(b1));
}
// bf16 helpers: pack(lo = elem k, hi = elem k+1)
__device__ __forceinline__ u32 bfp(float lo, float hi) {
    u32 r; asm("cvt.rn.bf16x2.f32 %0,%1,%2;" : "=r"(r) : "f"(hi), "f"(lo)); return r;
}
__device__ __forceinline__ void mma16(float4& c, u32 a0, u32 a1, u32 a2, u32 a3,
                                      u32 b0, u32 b1) {
    asm("mma.sync.aligned.m16n8k16.row.col.f32.bf16.bf16.f32 "
        "{%0,%1,%2,%3},{%4,%5,%6,%7},{%8,%9},{%0,%1,%2,%3};"
        : "+f"(c.x), "+f"(c.y), "+f"(c.z), "+f"(c.w)
        : "r"(a0), "r"(a1), "r"(a2), "r"(a3), "r"(b0), "r"(b1));
}

// Scratch (module-scope device arrays; no runtime allocation)
__device__ float g_x[BB * NN * DD];                 // activations  [B,N,D]
__device__ float g_part[NSPLIT * 2 * BB * KK * DD]; // split-N partials
__device__ float g_kvlow[2 * BB * KK * DD];         // reduced k_low / v_low
__device__ float g_kt[BB * DD * KK];                // k transposed  [b][d][k]
__device__ float g_v[BB * KK * DD];                 // v             [b][k][d]

// ---------------------------------------------------------------------------
// x[b,n,d] = emb[n,d] * expr[b,n]
__global__ void embed_kernel(const float* __restrict__ expr,
                             const float* __restrict__ emb) {
    int idx = blockIdx.x * blockDim.x + threadIdx.x;
    if (idx >= BB * NN) return;
    int b = idx / NN, n = idx % NN;
    float e = expr[b * NN + n];
    const float4* er = (const float4*)&emb[(size_t)n * DD];
    float4* xo = (float4*)&g_x[(size_t)idx * DD];
#pragma unroll
    for (int i = 0; i < DD / 4; i++) {
        float4 v = er[i];
        v.x *= e; v.y *= e; v.z *= e; v.w *= e;
        xo[i] = v;
    }
}

// ---------------------------------------------------------------------------
// Split-N low-rank projection with tf32 mma.sync (R11: 16-row chunks).
__global__ __launch_bounds__(256) void proj_mma_kernel(const float* __restrict__ PK,
                                                       const float* __restrict__ PV) {
    __shared__ u32 sPu[16 * 264];
    __shared__ u32 sXu[16 * 72];
    int s = blockIdx.x, b = blockIdx.y, mat = blockIdx.z;
    const float* P = (mat == 0) ? PK : PV;
    int t = threadIdx.x;
    int w = t >> 5, L = t & 31, g = L >> 2, t4 = L & 3;

    float4 C[2][8];
#pragma unroll
    for (int i = 0; i < 2; i++)
#pragma unroll
        for (int j = 0; j < 8; j++) C[i][j] = make_float4(0.f, 0.f, 0.f, 0.f);

    int n0 = (s * NN) / NSPLIT;
    int n1 = ((s + 1) * NN) / NSPLIT;

    for (int n = n0; n < n1; n += 16) {
        __syncthreads();
#pragma unroll
        for (int j = 0; j < 4; j++) {
            int e = (t + j * 256) * 4;
            int row = e >> 8, col = e & 255;
            int nr = n + row;
            uint4 u;
            if (nr < n1) {
                float4 v = *(const float4*)&P[(size_t)nr * KK + col];
                u.x = tf32c(v.x); u.y = tf32c(v.y); u.z = tf32c(v.z); u.w = tf32c(v.w);
            } else u = make_uint4(0, 0, 0, 0);
            *(uint4*)&sPu[row * 264 + col] = u;
        }
        {
            int e = t * 4;
            int row = e >> 6, col = e & 63;
            int nr = n + row;
            uint4 u;
            if (nr < n1) {
                float4 v = *(const float4*)&g_x[((size_t)b * NN + nr) * DD + col];
                u.x = tf32c(v.x); u.y = tf32c(v.y); u.z = tf32c(v.z); u.w = tf32c(v.w);
            } else u = make_uint4(0, 0, 0, 0);
            *(uint4*)&sXu[row * 72 + col] = u;
        }
        __syncthreads();

#pragma unroll
        for (int ks = 0; ks < 2; ks++) {
            int kr0 = (ks * 8 + t4) * 264;
            int kr1 = (ks * 8 + t4 + 4) * 264;
            u32 a[2][4];
#pragma unroll
            for (int mt = 0; mt < 2; mt++) {
                int m0 = w * 32 + mt * 16;
                a[mt][0] = sPu[kr0 + m0 + g];
                a[mt][1] = sPu[kr0 + m0 + g + 8];
                a[mt][2] = sPu[kr1 + m0 + g];
                a[mt][3] = sPu[kr1 + m0 + g + 8];
            }
            int xr0 = (ks * 8 + t4) * 72;
            int xr1 = (ks * 8 + t4 + 4) * 72;
#pragma unroll
            for (int nb = 0; nb < 8; nb++) {
                u32 b0 = sXu[xr0 + nb * 8 + g];
                u32 b1 = sXu[xr1 + nb * 8 + g];
                mma8(C[0][nb], a[0][0], a[0][1], a[0][2], a[0][3], b0, b1);
                mma8(C[1][nb], a[1][0], a[1][1], a[1][2], a[1][3], b0, b1);
            }
        }
    }

    float* o = g_part + (((size_t)s * 2 + mat) * BB + b) * (KK * DD);
#pragma unroll
    for (int mt = 0; mt < 2; mt++) {
        int m0 = w * 32 + mt * 16;
#pragma unroll
        for (int nb = 0; nb < 8; nb++) {
            int col = nb * 8 + 2 * t4;
            *(float2*)&o[(m0 + g) * DD + col] = make_float2(C[mt][nb].x, C[mt][nb].y);
            *(float2*)&o[(m0 + g + 8) * DD + col] = make_float2(C[mt][nb].z, C[mt][nb].w);
        }
    }
}

// ---------------------------------------------------------------------------
__global__ void reduce_kernel() {
    int idx = blockIdx.x * blockDim.x + threadIdx.x;
    if (idx >= 2 * BB * KK * DD) return;
    float sum = 0.f;
    for (int s = 0; s < NSPLIT; s++)
        sum += g_part[(size_t)s * (2 * BB * KK * DD) + idx];
    g_kvlow[idx] = sum;
}

// ---------------------------------------------------------------------------
// k/v head projections; K written transposed for the attention MMA.
__global__ void kvproj_kernel(const float* __restrict__ Wk,
                              const float* __restrict__ Wv) {
    int mat = blockIdx.z, b = blockIdx.y;
    const float* W = (mat == 0) ? Wk : Wv;
    __shared__ float sW[DD * DD];
    __shared__ float sL[4][DD];
    int t = threadIdx.x;
    for (int i = t * 4; i < DD * DD; i += 1024)
        *(float4*)&sW[i] = *(const float4*)&W[i];
    if (t < 64) {
        int r = t >> 4, c = (t & 15) * 4;
        int k = blockIdx.x * 4 + r;
        *(float4*)&sL[r][c] =
            *(const float4*)&g_kvlow[((size_t)mat * BB + b) * KK * DD + k * DD + c];
    }
    __syncthreads();
    int e = t & 63, kr = t >> 6;
    int k = blockIdx.x * 4 + kr;
    float sacc = 0.f;
#pragma unroll
    for (int d = 0; d < DD; d++) sacc += sL[kr][d] * sW[d * DD + e];
    if (mat == 0) {
        g_kt[((size_t)b * DD + e) * KK + k] = sacc;
    } else {
        g_v[(size_t)b * KK * DD + k * DD + e] = sacc;
    }
}

// ---------------------------------------------------------------------------
// Fused attention with tf32 mma.sync (R11 configuration, unchanged).
__global__ __launch_bounds__(256, 2) void attn_mma_kernel(const float* __restrict__ Wq,
                                                          const float* __restrict__ Wo,
                                                          const float* __restrict__ bo,
                                                          const float* __restrict__ g1,
                                                          const float* __restrict__ be1) {
    extern __shared__ u32 smu[];
    u32* sQ = smu;                        // [128][72] tf32
    u32* sP = sQ + 128 * 72;              // [128][72] tf32 (P, later O)
    u32* sC = sP + 128 * 72;              // [2][64][72]: Wq | (KT,V) | Wo
    float* sBo = (float*)(sC + 2 * 64 * 72);
    float* sG = sBo + 64;
    float* sBe = sG + 64;

    int b = blockIdx.y, t = threadIdx.x;
    int w = t >> 5, L = t & 31, g = L >> 2, t4 = L & 3;
    int row0 = blockIdx.x * 128;
    int rg = row0 + w * 16 + g;
    int rg8 = rg + 8;
    bool vg = rg < NN, vg8 = rg8 < NN;
    const float* xbase = g_x + (size_t)b * NN * DD;
    int rq = w * 16 + g;

    if (t < 16) {
        *(float4*)&sBo[t * 4] = *(const float4*)&bo[t * 4];
        *(float4*)&sG[t * 4] = *(const float4*)&g1[t * 4];
        *(float4*)&sBe[t * 4] = *(const float4*)&be1[t * 4];
    }
#pragma unroll
    for (int j = 0; j < 4; j++) {
        int e = (t + j * 256) * 4;
        int r = e >> 6, c = e & 63;
        float4 v = *(const float4*)&Wq[r * DD + c];
        *(uint4*)&sC[r * 72 + c] =
            make_uint4(tf32c(v.x), tf32c(v.y), tf32c(v.z), tf32c(v.w));
    }
    __syncthreads();

    // Q = X @ Wq
    {
        float4 CQ[8];
#pragma unroll
        for (int nb = 0; nb < 8; nb++) CQ[nb] = make_float4(0.f, 0.f, 0.f, 0.f);
#pragma unroll
        for (int ks = 0; ks < 8; ks++) {
            u32 a0 = tf32c(vg ? xbase[(size_t)rg * DD + ks * 8 + t4] : 0.f);
            u32 a1 = tf32c(vg8 ? xbase[(size_t)rg8 * DD + ks * 8 + t4] : 0.f);
            u32 a2 = tf32c(vg ? xbase[(size_t)rg * DD + ks * 8 + t4 + 4] : 0.f);
            u32 a3 = tf32c(vg8 ? xbase[(size_t)rg8 * DD + ks * 8 + t4 + 4] : 0.f);
            int wr0 = (ks * 8 + t4) * 72;
            int wr1 = (ks * 8 + t4 + 4) * 72;
#pragma unroll
            for (int nb = 0; nb < 8; nb++) {
                u32 b0 = sC[wr0 + nb * 8 + g];
                u32 b1 = sC[wr1 + nb * 8 + g];
                mma8(CQ[nb], a0, a1, a2, a3, b0, b1);
            }
        }
#pragma unroll
        for (int nb = 0; nb < 8; nb++) {
            int col = nb * 8 + 2 * t4;
            *(uint2*)&sQ[rq * 72 + col] = make_uint2(tf32c(CQ[nb].x), tf32c(CQ[nb].y));
            *(uint2*)&sQ[(rq + 8) * 72 + col] =
                make_uint2(tf32c(CQ[nb].z), tf32c(CQ[nb].w));
        }
    }

    const float* ktb = g_kt + (size_t)b * DD * KK;   // [d][256]
    const float* vb = g_v + (size_t)b * KK * DD;     // [k][64]

    float lx[HH], lz[HH];
    float4 O[HH][2];
#pragma unroll
    for (int h = 0; h < HH; h++) {
        lx[h] = 0.f; lz[h] = 0.f;
        O[h][0] = make_float4(0.f, 0.f, 0.f, 0.f);
        O[h][1] = make_float4(0.f, 0.f, 0.f, 0.f);
    }

#pragma unroll 1
    for (int chunk = 0; chunk < 4; chunk++) {
        int k0 = chunk * 64;
        __syncthreads();
#pragma unroll
        for (int j = 0; j < 4; j++) {
            int e = (t + j * 256) * 4;
            int r = e >> 6, c = e & 63;
            float4 kv = *(const float4*)&ktb[(size_t)r * KK + k0 + c];
            *(uint4*)&sC[r * 72 + c] =
                make_uint4(tf32c(kv.x), tf32c(kv.y), tf32c(kv.z), tf32c(kv.w));
            float4 vv = *(const float4*)&vb[(size_t)(k0 + r) * DD + c];
            *(uint4*)&sC[64 * 72 + r * 72 + c] =
                make_uint4(tf32c(vv.x), tf32c(vv.y), tf32c(vv.z), tf32c(vv.w));
        }
        __syncthreads();

#pragma unroll
        for (int h = 0; h < HH; h++) {
            float4 CS[8];
#pragma unroll
            for (int nb = 0; nb < 8; nb++) CS[nb] = make_float4(0.f, 0.f, 0.f, 0.f);
#pragma unroll
            for (int ks = 0; ks < 2; ks++) {
                int kd = h * 16 + ks * 8;
                u32 a0 = sQ[rq * 72 + kd + t4];
                u32 a1 = sQ[(rq + 8) * 72 + kd + t4];
                u32 a2 = sQ[rq * 72 + kd + t4 + 4];
                u32 a3 = sQ[(rq + 8) * 72 + kd + t4 + 4];
                int wr0 = (kd + t4) * 72;
                int wr1 = (kd + t4 + 4) * 72;
#pragma unroll
                for (int nb = 0; nb < 8; nb++) {
                    u32 b0 = sC[wr0 + nb * 8 + g];
                    u32 b1 = sC[wr1 + nb * 8 + g];
                    mma8(CS[nb], a0, a1, a2, a3, b0, b1);
                }
            }
#pragma unroll
            for (int nb = 0; nb < 8; nb++) {
                float px = __expf(CS[nb].x * 0.25f);
                float py = __expf(CS[nb].y * 0.25f);
                float pz = __expf(CS[nb].z * 0.25f);
                float pw = __expf(CS[nb].w * 0.25f);
                lx[h] += px + py;
                lz[h] += pz + pw;
                int col = nb * 8 + 2 * t4;
                *(uint2*)&sP[rq * 72 + col] = make_uint2(tf32c(px), tf32c(py));
                *(uint2*)&sP[(rq + 8) * 72 + col] = make_uint2(tf32c(pz), tf32c(pw));
            }
            __syncwarp();
#pragma unroll
            for (int ks = 0; ks < 8; ks++) {
                u32 a0 = sP[rq * 72 + ks * 8 + t4];
                u32 a1 = sP[(rq + 8) * 72 + ks * 8 + t4];
                u32 a2 = sP[rq * 72 + ks * 8 + t4 + 4];
                u32 a3 = sP[(rq + 8) * 72 + ks * 8 + t4 + 4];
                int vr0 = 64 * 72 + (ks * 8 + t4) * 72;
                int vr1 = 64 * 72 + (ks * 8 + t4 + 4) * 72;
#pragma unroll
                for (int nb = 0; nb < 2; nb++) {
                    u32 b0 = sC[vr0 + h * 16 + nb * 8 + g];
                    u32 b1 = sC[vr1 + h * 16 + nb * 8 + g];
                    mma8(O[h][nb], a0, a1, a2, a3, b0, b1);
                }
            }
            __syncwarp();
        }
    }

#pragma unroll
    for (int h = 0; h < HH; h++) {
        lx[h] += __shfl_xor_sync(0xffffffffu, lx[h], 1);
        lx[h] += __shfl_xor_sync(0xffffffffu, lx[h], 2);
        lz[h] += __shfl_xor_sync(0xffffffffu, lz[h], 1);
        lz[h] += __shfl_xor_sync(0xffffffffu, lz[h], 2);
    }
#pragma unroll
    for (int h = 0; h < HH; h++) {
        float ix = 1.f / lx[h], iz = 1.f / lz[h];
#pragma unroll
        for (int nb = 0; nb < 2; nb++) {
            int col = h * 16 + nb * 8 + 2 * t4;
            *(uint2*)&sP[rq * 72 + col] =
                make_uint2(tf32c(O[h][nb].x * ix), tf32c(O[h][nb].y * ix));
            *(uint2*)&sP[(rq + 8) * 72 + col] =
                make_uint2(tf32c(O[h][nb].z * iz), tf32c(O[h][nb].w * iz));
        }
    }
    __syncthreads();
#pragma unroll
    for (int j = 0; j < 4; j++) {
        int e = (t + j * 256) * 4;
        int r = e >> 6, c = e & 63;
        float4 v = *(const float4*)&Wo[r * DD + c];
        *(uint4*)&sC[r * 72 + c] =
            make_uint4(tf32c(v.x), tf32c(v.y), tf32c(v.z), tf32c(v.w));
    }
    __syncthreads();

    float4 C2[8];
#pragma unroll
    for (int nb = 0; nb < 8; nb++) C2[nb] = make_float4(0.f, 0.f, 0.f, 0.f);
#pragma unroll
    for (int ks = 0; ks < 8; ks++) {
        u32 a0 = sP[rq * 72 + ks * 8 + t4];
        u32 a1 = sP[(rq + 8) * 72 + ks * 8 + t4];
        u32 a2 = sP[rq * 72 + ks * 8 + t4 + 4];
        u32 a3 = sP[(rq + 8) * 72 + ks * 8 + t4 + 4];
        int wr0 = (ks * 8 + t4) * 72;
        int wr1 = (ks * 8 + t4 + 4) * 72;
#pragma unroll
        for (int nb = 0; nb < 8; nb++) {
            u32 b0 = sC[wr0 + nb * 8 + g];
            u32 b1 = sC[wr1 + nb * 8 + g];
            mma8(C2[nb], a0, a1, a2, a3, b0, b1);
        }
    }

#pragma unroll 1
    for (int rp = 0; rp < 2; rp++) {
        int r = rp ? rg8 : rg;
        bool vr = rp ? vg8 : vg;
        float vx[8], vy[8];
#pragma unroll
        for (int nb = 0; nb < 8; nb++) {
            int col = nb * 8 + 2 * t4;
            float2 xv = vr ? *(const float2*)&xbase[(size_t)r * DD + col]
                           : make_float2(0.f, 0.f);
            float cva = rp ? C2[nb].z : C2[nb].x;
            float cvb = rp ? C2[nb].w : C2[nb].y;
            vx[nb] = cva + sBo[col] + xv.x;
            vy[nb] = cvb + sBo[col + 1] + xv.y;
        }
        float s = 0.f;
#pragma unroll
        for (int nb = 0; nb < 8; nb++) s += vx[nb] + vy[nb];
        s += __shfl_xor_sync(0xffffffffu, s, 1);
        s += __shfl_xor_sync(0xffffffffu, s, 2);
        float m = s * (1.f / DD);
        float q = 0.f;
#pragma unroll
        for (int nb = 0; nb < 8; nb++) {
            float d0 = vx[nb] - m, d1 = vy[nb] - m;
            q += d0 * d0 + d1 * d1;
        }
        q += __shfl_xor_sync(0xffffffffu, q, 1);
        q += __shfl_xor_sync(0xffffffffu, q, 2);
        float inv = rsqrtf(q * (1.f / DD) + 1e-5f);
        if (vr) {
            float* op = g_x + ((size_t)b * NN + r) * DD;
#pragma unroll
            for (int nb = 0; nb < 8; nb++) {
                int col = nb * 8 + 2 * t4;
                float2 o2;
                o2.x = (vx[nb] - m) * inv * sG[col] + sBe[col];
                o2.y = (vy[nb] - m) * inv * sG[col + 1] + sBe[col + 1];
                *(float2*)&op[col] = o2;
            }
        }
    }
}

// ---------------------------------------------------------------------------
// Fused FFN with bf16 mma.sync.m16n8k16:
//   H = gelu(X@W1 + b1); F = H@W2 + b2; out = LN2(F + X)
// X staged once in smem as packed bf16 pairs; W1/W2 per-64-f chunk.
// Layouts: A-type [row][36] u32 (kpair t4 / t4+4); B-type [32 kpair][72] u32.
__global__ __launch_bounds__(256, 2) void ffn_mma_kernel(const float* __restrict__ W1,
                                                         const float* __restrict__ b1,
                                                         const float* __restrict__ W2,
                                                         const float* __restrict__ b2,
                                                         const float* __restrict__ g2,
                                                         const float* __restrict__ be2,
                                                         float* __restrict__ xout) {
    extern __shared__ u32 smu[];
    u32* sX = smu;                        // [128][36] bf16x2
    u32* sH = sX + 128 * 36;              // [128][36] bf16x2
    u32* sW1u = sH + 128 * 36;            // [32 kpair][72] bf16x2
    u32* sW2u = sW1u + 32 * 72;           // [32 kpair][72] bf16x2
    float* sB1 = (float*)(sW2u + 32 * 72);
    float* sB2 = sB1 + 256;
    float* sG = sB2 + 64;
    float* sBe = sG + 64;

    int b = blockIdx.y, t = threadIdx.x;
    int w = t >> 5, L = t & 31, g = L >> 2, t4 = L & 3;
    int row0 = blockIdx.x * 128;

    if (t < 64) *(float4*)&sB1[t * 4] = *(const float4*)&b1[t * 4];
    if (t < 16) {
        *(float4*)&sB2[t * 4] = *(const float4*)&b2[t * 4];
        *(float4*)&sG[t * 4] = *(const float4*)&g2[t * 4];
        *(float4*)&sBe[t * 4] = *(const float4*)&be2[t * 4];
    }

    const float* xbase = g_x + (size_t)b * NN * DD;
    int rg = row0 + w * 16 + g;
    int rg8 = rg + 8;
    bool vg = rg < NN, vg8 = rg8 < NN;
    int rq = w * 16 + g;

    // stage X [128 rows][64 d] -> bf16 pairs, rows beyond NN zeroed
#pragma unroll
    for (int j = 0; j < 8; j++) {
        int idx = t + j * 256;            // 2048 float4-groups
        int r = idx >> 4, c4 = idx & 15;  // row, float4 index (0..15)
        int nr = row0 + r;
        uint2 u;
        if (nr < NN) {
            float4 v = *(const float4*)&xbase[(size_t)nr * DD + c4 * 4];
            u = make_uint2(bfp(v.x, v.y), bfp(v.z, v.w));
        } else u = make_uint2(0u, 0u);
        *(uint2*)&sX[r * 36 + c4 * 2] = u;
    }

    float4 C2[8];
#pragma unroll
    for (int nb = 0; nb < 8; nb++) C2[nb] = make_float4(0.f, 0.f, 0.f, 0.f);

#pragma unroll 1
    for (int fc = 0; fc < 4; fc++) {
        int f0 = fc * 64;
        __syncthreads();
        // stage W1 chunk [64 d][64 f] and W2 chunk [64 f][64 d] as bf16 pairs,
        // packed along the k (reduction) dimension.
#pragma unroll
        for (int j = 0; j < 8; j++) {
            int idx = t + j * 256;        // 2048 words
            int kp = idx >> 6, c = idx & 63;
            float lo1 = W1[(2 * kp) * FF + f0 + c];
            float hi1 = W1[(2 * kp + 1) * FF + f0 + c];
            sW1u[kp * 72 + c] = bfp(lo1, hi1);
            float lo2 = W2[(size_t)(f0 + 2 * kp) * DD + c];
            float hi2 = W2[(size_t)(f0 + 2 * kp + 1) * DD + c];
            sW2u[kp * 72 + c] = bfp(lo2, hi2);
        }
        __syncthreads();

        // GEMM1: C1[16 rows x 64 f] = X[16 x 64] @ W1chunk  (4 k16 steps)
        float4 C1[8];
#pragma unroll
        for (int nb = 0; nb < 8; nb++) {
            int col = f0 + nb * 8 + 2 * t4;
            C1[nb] = make_float4(sB1[col], sB1[col + 1], sB1[col], sB1[col + 1]);
        }
#pragma unroll
        for (int ks = 0; ks < 4; ks++) {
            u32 a0 = sX[rq * 36 + ks * 8 + t4];
            u32 a1 = sX[(rq + 8) * 36 + ks * 8 + t4];
            u32 a2 = sX[rq * 36 + ks * 8 + t4 + 4];
            u32 a3 = sX[(rq + 8) * 36 + ks * 8 + t4 + 4];
            int wr0 = (ks * 8 + t4) * 72;
            int wr1 = (ks * 8 + t4 + 4) * 72;
#pragma unroll
            for (int nb = 0; nb < 8; nb++) {
                u32 b0 = sW1u[wr0 + nb * 8 + g];
                u32 b1r = sW1u[wr1 + nb * 8 + g];
                mma16(C1[nb], a0, a1, a2, a3, b0, b1r);
            }
        }
        // GELU (exact) + store H as bf16 pairs (warp-private rows)
#pragma unroll
        for (int nb = 0; nb < 8; nb++) {
            float h0 = C1[nb].x, h1 = C1[nb].y, h2 = C1[nb].z, h3 = C1[nb].w;
            h0 = 0.5f * h0 * (1.f + erff(h0 * 0.70710678118654752440f));
            h1 = 0.5f * h1 * (1.f + erff(h1 * 0.70710678118654752440f));
            h2 = 0.5f * h2 * (1.f + erff(h2 * 0.70710678118654752440f));
            h3 = 0.5f * h3 * (1.f + erff(h3 * 0.70710678118654752440f));
            int kp = nb * 4 + t4;         // kpair index of cols (nb*8+2t4, +1)
            sH[rq * 36 + kp] = bfp(h0, h1);
            sH[(rq + 8) * 36 + kp] = bfp(h2, h3);
        }
        __syncwarp();
        // GEMM2: C2[16 rows x 64 d] += H[16 x 64] @ W2chunk
#pragma unroll
        for (int ks = 0; ks < 4; ks++) {
            u32 a0 = sH[rq * 36 + ks * 8 + t4];
            u32 a1 = sH[(rq + 8) * 36 + ks * 8 + t4];
            u32 a2 = sH[rq * 36 + ks * 8 + t4 + 4];
            u32 a3 = sH[(rq + 8) * 36 + ks * 8 + t4 + 4];
            int wr0 = (ks * 8 + t4) * 72;
            int wr1 = (ks * 8 + t4 + 4) * 72;
#pragma unroll
            for (int nb = 0; nb < 8; nb++) {
                u32 b0 = sW2u[wr0 + nb * 8 + g];
                u32 b1r = sW2u[wr1 + nb * 8 + g];
                mma16(C2[nb], a0, a1, a2, a3, b0, b1r);
            }
        }
        __syncwarp();
    }

    // Epilogue: +b2, +residual x (fp32 from gmem), LayerNorm, store.
#pragma unroll 1
    for (int rp = 0; rp < 2; rp++) {
        int r = rp ? rg8 : rg;
        bool vr = rp ? vg8 : vg;
        float vx[8], vy[8];
#pragma unroll
        for (int nb = 0; nb < 8; nb++) {
            int col = nb * 8 + 2 * t4;
            float2 xv = vr ? *(const float2*)&xbase[(size_t)r * DD + col]
                           : make_float2(0.f, 0.f);
            float cva = rp ? C2[nb].z : C2[nb].x;
            float cvb = rp ? C2[nb].w : C2[nb].y;
            vx[nb] = cva + sB2[col] + xv.x;
            vy[nb] = cvb + sB2[col + 1] + xv.y;
        }
        float s = 0.f;
#pragma unroll
        for (int nb = 0; nb < 8; nb++) s += vx[nb] + vy[nb];
        s += __shfl_xor_sync(0xffffffffu, s, 1);
        s += __shfl_xor_sync(0xffffffffu, s, 2);
        float m = s * (1.f / DD);
        float q = 0.f;
#pragma unroll
        for (int nb = 0; nb < 8; nb++) {
            float d0 = vx[nb] - m, d1 = vy[nb] - m;
            q += d0 * d0 + d1 * d1;
        }
        q += __shfl_xor_sync(0xffffffffu, q, 1);
        q += __shfl_xor_sync(0xffffffffu, q, 2);
        float inv = rsqrtf(q * (1.f / DD) + 1e-5f);
        if (vr) {
            float* op = xout + ((size_t)b * NN + r) * DD;
#pragma unroll
            for (int nb = 0; nb < 8; nb++) {
                int col = nb * 8 + 2 * t4;
                float2 o2;
                o2.x = (vx[nb] - m) * inv * sG[col] + sBe[col];
                o2.y = (vy[nb] - m) * inv * sG[col + 1] + sBe[col + 1];
                *(float2*)&op[col] = o2;
            }
        }
    }
}

// ---------------------------------------------------------------------------
extern "C" void kernel_launch(void* const* d_in, const int* in_sizes, int n_in,
                              void* d_out, int out_size) {
    const float* expr = (const float*)d_in[0];
    const float* emb = (const float*)d_in[1];
    const float* Wq = (const float*)d_in[2];
    const float* Wk = (const float*)d_in[3];
    const float* Wv = (const float*)d_in[4];
    const float* projK = (const float*)d_in[5];
    const float* projV = (const float*)d_in[6];
    const float* Wo = (const float*)d_in[7];
    const float* bo = (const float*)d_in[8];
    const float* g1 = (const float*)d_in[9];
    const float* be1 = (const float*)d_in[10];
    const float* W1 = (const float*)d_in[11];
    const float* bf1 = (const float*)d_in[12];
    const float* W2 = (const float*)d_in[13];
    const float* bf2 = (const float*)d_in[14];
    const float* g2 = (const float*)d_in[15];
    const float* be2 = (const float*)d_in[16];
    float* out = (float*)d_out;

    void* xaddr = nullptr;
    cudaGetSymbolAddress(&xaddr, g_x);
    float* gx = (float*)xaddr;

    cudaFuncSetAttribute(attn_mma_kernel, cudaFuncAttributeMaxDynamicSharedMemorySize,
                         ATTN_SMEM_BYTES);
    cudaFuncSetAttribute(ffn_mma_kernel, cudaFuncAttributeMaxDynamicSharedMemorySize,
                         FFN_SMEM_BYTES);

    embed_kernel<<<(BB * NN + 255) / 256, 256>>>(expr, emb);

    for (int l = 0; l < LLAYERS; l++) {
        proj_mma_kernel<<<dim3(NSPLIT, BB, 2), 256>>>(projK + (size_t)l * NN * KK,
                                                      projV + (size_t)l * NN * KK);
        reduce_kernel<<<(2 * BB * KK * DD) / 256, 256>>>();
        kvproj_kernel<<<dim3(KK / 4, BB, 2), 256>>>(Wk + l * DD * DD,
                                                    Wv + l * DD * DD);
        attn_mma_kernel<<<dim3(ATILES, BB), 256, ATTN_SMEM_BYTES>>>(
            Wq + l * DD * DD, Wo + l * DD * DD, bo + l * DD, g1 + l * DD,
            be1 + l * DD);
        ffn_mma_kernel<<<dim3(ATILES, BB), 256, FFN_SMEM_BYTES>>>(
            W1 + (size_t)l * DD * FF, bf1 + l * FF, W2 + (size_t)l * FF * DD,
            bf2 + l * DD, g2 + l * DD, be2 + l * DD,
            (l == LLAYERS - 1) ? out : gx);
    }
}

// round 17
// speedup vs baseline: 1.6138x; 1.2240x over previous
#include <cuda_runtime.h>
#include <cuda_bf16.h>
#include <math.h>

// Problem constants
#define BB 4
#define NN 20000
#define DD 64
#define KK 256
#define HH 4
#define DHD 16
#define FF 256
#define LLAYERS 2
#define NSPLIT 37
#define ATILES 157                   // 157*128 = 20096 >= 20000

// attn bf16 smem: sQ[128*36] + sP[128*36] + sC[2*32*72] + consts 192
#define ATTN_SMEM_WORDS (128 * 36 + 128 * 36 + 2 * 32 * 72 + 64 + 64 + 64)
#define ATTN_SMEM_BYTES (ATTN_SMEM_WORDS * 4)                         // 56064
// ffn bf16 smem: sX[128*36] + sH[128*36] + sW1[32*72] + sW2[32*72] + b1/b2/g/be
#define FFN_SMEM_WORDS (128 * 36 + 128 * 36 + 32 * 72 + 32 * 72 + 256 + 64 + 64 + 64)
#define FFN_SMEM_BYTES (FFN_SMEM_WORDS * 4)                           // 57088

typedef unsigned long long u64;
typedef unsigned int u32;

// tf32 helpers
__device__ __forceinline__ u32 tf32c(float v) {
    u32 r; asm("cvt.rna.tf32.f32 %0,%1;" : "=r"(r) : "f"(v)); return r;
}
__device__ __forceinline__ void mma8(float4& c, u32 a0, u32 a1, u32 a2, u32 a3,
                                     u32 b0, u32 b1) {
    asm("mma.sync.aligned.m16n8k8.row.col.f32.tf32.tf32.f32 "
        "{%0,%1,%2,%3},{%4,%5,%6,%7},{%8,%9},{%0,%1,%2,%3};"
        : "+f"(c.x), "+f"(c.y), "+f"(c.z), "+f"(c.w)
        : "r"(a0), "r"(a1), "r"(a2), "r"(a3), "r"(b0), "r"(b1));
}
// bf16 helpers: pack(lo = elem k, hi = elem k+1)
__device__ __forceinline__ u32 bfp(float lo, float hi) {
    u32 r; asm("cvt.rn.bf16x2.f32 %0,%1,%2;" : "=r"(r) : "f"(hi), "f"(lo)); return r;
}
__device__ __forceinline__ void mma16(float4& c, u32 a0, u32 a1, u32 a2, u32 a3,
                                      u32 b0, u32 b1) {
    asm("mma.sync.aligned.m16n8k16.row.col.f32.bf16.bf16.f32 "
        "{%0,%1,%2,%3},{%4,%5,%6,%7},{%8,%9},{%0,%1,%2,%3};"
        : "+f"(c.x), "+f"(c.y), "+f"(c.z), "+f"(c.w)
        : "r"(a0), "r"(a1), "r"(a2), "r"(a3), "r"(b0), "r"(b1));
}

// Scratch (module-scope device arrays; no runtime allocation)
__device__ float g_x[BB * NN * DD];                 // activations  [B,N,D]
__device__ float g_part[NSPLIT * 2 * BB * KK * DD]; // split-N partials
__device__ float g_kvlow[2 * BB * KK * DD];         // reduced k_low / v_low
__device__ float g_kt[BB * DD * KK];                // k transposed  [b][d][k]
__device__ float g_v[BB * KK * DD];                 // v             [b][k][d]

// ---------------------------------------------------------------------------
// x[b,n,d] = emb[n,d] * expr[b,n]
__global__ void embed_kernel(const float* __restrict__ expr,
                             const float* __restrict__ emb) {
    int idx = blockIdx.x * blockDim.x + threadIdx.x;
    if (idx >= BB * NN) return;
    int b = idx / NN, n = idx % NN;
    float e = expr[b * NN + n];
    const float4* er = (const float4*)&emb[(size_t)n * DD];
    float4* xo = (float4*)&g_x[(size_t)idx * DD];
#pragma unroll
    for (int i = 0; i < DD / 4; i++) {
        float4 v = er[i];
        v.x *= e; v.y *= e; v.z *= e; v.w *= e;
        xo[i] = v;
    }
}

// ---------------------------------------------------------------------------
// Split-N low-rank projection with tf32 mma.sync (R11: 16-row chunks).
__global__ __launch_bounds__(256) void proj_mma_kernel(const float* __restrict__ PK,
                                                       const float* __restrict__ PV) {
    __shared__ u32 sPu[16 * 264];
    __shared__ u32 sXu[16 * 72];
    int s = blockIdx.x, b = blockIdx.y, mat = blockIdx.z;
    const float* P = (mat == 0) ? PK : PV;
    int t = threadIdx.x;
    int w = t >> 5, L = t & 31, g = L >> 2, t4 = L & 3;

    float4 C[2][8];
#pragma unroll
    for (int i = 0; i < 2; i++)
#pragma unroll
        for (int j = 0; j < 8; j++) C[i][j] = make_float4(0.f, 0.f, 0.f, 0.f);

    int n0 = (s * NN) / NSPLIT;
    int n1 = ((s + 1) * NN) / NSPLIT;

    for (int n = n0; n < n1; n += 16) {
        __syncthreads();
#pragma unroll
        for (int j = 0; j < 4; j++) {
            int e = (t + j * 256) * 4;
            int row = e >> 8, col = e & 255;
            int nr = n + row;
            uint4 u;
            if (nr < n1) {
                float4 v = *(const float4*)&P[(size_t)nr * KK + col];
                u.x = tf32c(v.x); u.y = tf32c(v.y); u.z = tf32c(v.z); u.w = tf32c(v.w);
            } else u = make_uint4(0, 0, 0, 0);
            *(uint4*)&sPu[row * 264 + col] = u;
        }
        {
            int e = t * 4;
            int row = e >> 6, col = e & 63;
            int nr = n + row;
            uint4 u;
            if (nr < n1) {
                float4 v = *(const float4*)&g_x[((size_t)b * NN + nr) * DD + col];
                u.x = tf32c(v.x); u.y = tf32c(v.y); u.z = tf32c(v.z); u.w = tf32c(v.w);
            } else u = make_uint4(0, 0, 0, 0);
            *(uint4*)&sXu[row * 72 + col] = u;
        }
        __syncthreads();

#pragma unroll
        for (int ks = 0; ks < 2; ks++) {
            int kr0 = (ks * 8 + t4) * 264;
            int kr1 = (ks * 8 + t4 + 4) * 264;
            u32 a[2][4];
#pragma unroll
            for (int mt = 0; mt < 2; mt++) {
                int m0 = w * 32 + mt * 16;
                a[mt][0] = sPu[kr0 + m0 + g];
                a[mt][1] = sPu[kr0 + m0 + g + 8];
                a[mt][2] = sPu[kr1 + m0 + g];
                a[mt][3] = sPu[kr1 + m0 + g + 8];
            }
            int xr0 = (ks * 8 + t4) * 72;
            int xr1 = (ks * 8 + t4 + 4) * 72;
#pragma unroll
            for (int nb = 0; nb < 8; nb++) {
                u32 b0 = sXu[xr0 + nb * 8 + g];
                u32 b1 = sXu[xr1 + nb * 8 + g];
                mma8(C[0][nb], a[0][0], a[0][1], a[0][2], a[0][3], b0, b1);
                mma8(C[1][nb], a[1][0], a[1][1], a[1][2], a[1][3], b0, b1);
            }
        }
    }

    float* o = g_part + (((size_t)s * 2 + mat) * BB + b) * (KK * DD);
#pragma unroll
    for (int mt = 0; mt < 2; mt++) {
        int m0 = w * 32 + mt * 16;
#pragma unroll
        for (int nb = 0; nb < 8; nb++) {
            int col = nb * 8 + 2 * t4;
            *(float2*)&o[(m0 + g) * DD + col] = make_float2(C[mt][nb].x, C[mt][nb].y);
            *(float2*)&o[(m0 + g + 8) * DD + col] = make_float2(C[mt][nb].z, C[mt][nb].w);
        }
    }
}

// ---------------------------------------------------------------------------
__global__ void reduce_kernel() {
    int idx = blockIdx.x * blockDim.x + threadIdx.x;
    if (idx >= 2 * BB * KK * DD) return;
    float sum = 0.f;
    for (int s = 0; s < NSPLIT; s++)
        sum += g_part[(size_t)s * (2 * BB * KK * DD) + idx];
    g_kvlow[idx] = sum;
}

// ---------------------------------------------------------------------------
// k/v head projections; K written transposed for the attention MMA.
__global__ void kvproj_kernel(const float* __restrict__ Wk,
                              const float* __restrict__ Wv) {
    int mat = blockIdx.z, b = blockIdx.y;
    const float* W = (mat == 0) ? Wk : Wv;
    __shared__ float sW[DD * DD];
    __shared__ float sL[4][DD];
    int t = threadIdx.x;
    for (int i = t * 4; i < DD * DD; i += 1024)
        *(float4*)&sW[i] = *(const float4*)&W[i];
    if (t < 64) {
        int r = t >> 4, c = (t & 15) * 4;
        int k = blockIdx.x * 4 + r;
        *(float4*)&sL[r][c] =
            *(const float4*)&g_kvlow[((size_t)mat * BB + b) * KK * DD + k * DD + c];
    }
    __syncthreads();
    int e = t & 63, kr = t >> 6;
    int k = blockIdx.x * 4 + kr;
    float sacc = 0.f;
#pragma unroll
    for (int d = 0; d < DD; d++) sacc += sL[kr][d] * sW[d * DD + e];
    if (mat == 0) {
        g_kt[((size_t)b * DD + e) * KK + k] = sacc;
    } else {
        g_v[(size_t)b * KK * DD + k * DD + e] = sacc;
    }
}

// ---------------------------------------------------------------------------
// Fused attention with bf16 mma.sync.m16n8k16:
//   Q = X@Wq; S_h = Q_h @ K_h^T; P = exp(S/4); O_h = P_h @ V_h / l;
//   out = LN1(O @ Wo + bo + X)
// CTA = 128 rows, 256 threads (8 warps, warp = 16 rows). K in 4 chunks of 64.
// Packed layouts (all conflict-free):
//   sQ [128 row][36]: Q bf16 pairs packed along d
//   sP [128 row][36]: P pairs packed along chunk-k; later O pairs packed along d
//   sC [2][32 kpair][72]: Wq | (KT d-pairs, V k-pairs) | Wo
__global__ __launch_bounds__(256, 2) void attn_mma_kernel(const float* __restrict__ Wq,
                                                          const float* __restrict__ Wo,
                                                          const float* __restrict__ bo,
                                                          const float* __restrict__ g1,
                                                          const float* __restrict__ be1) {
    extern __shared__ u32 smu[];
    u32* sQ = smu;                        // [128][36]
    u32* sP = sQ + 128 * 36;              // [128][36]
    u32* sC = sP + 128 * 36;              // [2][32][72]
    float* sBo = (float*)(sC + 2 * 32 * 72);
    float* sG = sBo + 64;
    float* sBe = sG + 64;
    const int VOFF = 32 * 72;

    int b = blockIdx.y, t = threadIdx.x;
    int w = t >> 5, L = t & 31, g = L >> 2, t4 = L & 3;
    int row0 = blockIdx.x * 128;
    int rg = row0 + w * 16 + g;
    int rg8 = rg + 8;
    bool vg = rg < NN, vg8 = rg8 < NN;
    const float* xbase = g_x + (size_t)b * NN * DD;
    int rq = w * 16 + g;

    if (t < 16) {
        *(float4*)&sBo[t * 4] = *(const float4*)&bo[t * 4];
        *(float4*)&sG[t * 4] = *(const float4*)&g1[t * 4];
        *(float4*)&sBe[t * 4] = *(const float4*)&be1[t * 4];
    }
    // stage Wq as bf16 d-pairs: [32 kp][72]
#pragma unroll
    for (int j = 0; j < 8; j++) {
        int idx = t + j * 256;
        int kp = idx >> 6, c = idx & 63;
        sC[kp * 72 + c] = bfp(Wq[(2 * kp) * DD + c], Wq[(2 * kp + 1) * DD + c]);
    }
    __syncthreads();

    // Q = X @ Wq  (4 k16 steps; A straight from gmem as bf16 pairs)
    {
        float4 CQ[8];
#pragma unroll
        for (int nb = 0; nb < 8; nb++) CQ[nb] = make_float4(0.f, 0.f, 0.f, 0.f);
#pragma unroll
        for (int ks = 0; ks < 4; ks++) {
            float2 xa = vg ? *(const float2*)&xbase[(size_t)rg * DD + ks * 16 + 2 * t4]
                           : make_float2(0.f, 0.f);
            float2 xb = vg8 ? *(const float2*)&xbase[(size_t)rg8 * DD + ks * 16 + 2 * t4]
                            : make_float2(0.f, 0.f);
            float2 xc = vg ? *(const float2*)&xbase[(size_t)rg * DD + ks * 16 + 2 * t4 + 8]
                           : make_float2(0.f, 0.f);
            float2 xd = vg8 ? *(const float2*)&xbase[(size_t)rg8 * DD + ks * 16 + 2 * t4 + 8]
                            : make_float2(0.f, 0.f);
            u32 a0 = bfp(xa.x, xa.y), a1 = bfp(xb.x, xb.y);
            u32 a2 = bfp(xc.x, xc.y), a3 = bfp(xd.x, xd.y);
            int wr0 = (ks * 8 + t4) * 72;
            int wr1 = (ks * 8 + t4 + 4) * 72;
#pragma unroll
            for (int nb = 0; nb < 8; nb++) {
                u32 b0 = sC[wr0 + nb * 8 + g];
                u32 b1 = sC[wr1 + nb * 8 + g];
                mma16(CQ[nb], a0, a1, a2, a3, b0, b1);
            }
        }
        // store Q packed along d: col pair (nb*8+2t4)/2 = nb*4+t4
#pragma unroll
        for (int nb = 0; nb < 8; nb++) {
            sQ[rq * 36 + nb * 4 + t4] = bfp(CQ[nb].x, CQ[nb].y);
            sQ[(rq + 8) * 36 + nb * 4 + t4] = bfp(CQ[nb].z, CQ[nb].w);
        }
    }

    const float* ktb = g_kt + (size_t)b * DD * KK;   // [d][256]
    const float* vb = g_v + (size_t)b * KK * DD;     // [k][64]

    float lx[HH], lz[HH];
    float4 O[HH][2];
#pragma unroll
    for (int h = 0; h < HH; h++) {
        lx[h] = 0.f; lz[h] = 0.f;
        O[h][0] = make_float4(0.f, 0.f, 0.f, 0.f);
        O[h][1] = make_float4(0.f, 0.f, 0.f, 0.f);
    }

#pragma unroll 1
    for (int chunk = 0; chunk < 4; chunk++) {
        int k0 = chunk * 64;
        __syncthreads();
        // stage KT chunk as d-pairs [32 kp][64 k] and V chunk as k-pairs [32 kp][64 d]
#pragma unroll
        for (int j = 0; j < 8; j++) {
            int idx = t + j * 256;
            int kp = idx >> 6, c = idx & 63;
            sC[kp * 72 + c] = bfp(ktb[(size_t)(2 * kp) * KK + k0 + c],
                                  ktb[(size_t)(2 * kp + 1) * KK + k0 + c]);
            sC[VOFF + kp * 72 + c] = bfp(vb[(size_t)(k0 + 2 * kp) * DD + c],
                                         vb[(size_t)(k0 + 2 * kp + 1) * DD + c]);
        }
        __syncthreads();

#pragma unroll
        for (int h = 0; h < HH; h++) {
            // S_h = Q_h @ KT_h : single k16 step (DHD=16), 8 n-blocks
            float4 CS[8];
#pragma unroll
            for (int nb = 0; nb < 8; nb++) CS[nb] = make_float4(0.f, 0.f, 0.f, 0.f);
            {
                u32 a0 = sQ[rq * 36 + h * 8 + t4];
                u32 a1 = sQ[(rq + 8) * 36 + h * 8 + t4];
                u32 a2 = sQ[rq * 36 + h * 8 + t4 + 4];
                u32 a3 = sQ[(rq + 8) * 36 + h * 8 + t4 + 4];
                int wr0 = (h * 8 + t4) * 72;
                int wr1 = (h * 8 + t4 + 4) * 72;
#pragma unroll
                for (int nb = 0; nb < 8; nb++) {
                    u32 b0 = sC[wr0 + nb * 8 + g];
                    u32 b1 = sC[wr1 + nb * 8 + g];
                    mma16(CS[nb], a0, a1, a2, a3, b0, b1);
                }
            }
            // exp, accumulate l, store P packed along chunk-k
#pragma unroll
            for (int nb = 0; nb < 8; nb++) {
                float px = __expf(CS[nb].x * 0.25f);
                float py = __expf(CS[nb].y * 0.25f);
                float pz = __expf(CS[nb].z * 0.25f);
                float pw = __expf(CS[nb].w * 0.25f);
                lx[h] += px + py;
                lz[h] += pz + pw;
                sP[rq * 36 + nb * 4 + t4] = bfp(px, py);
                sP[(rq + 8) * 36 + nb * 4 + t4] = bfp(pz, pw);
            }
            __syncwarp();
            // O_h += P @ V_h : 4 k16 steps, 2 n-blocks
#pragma unroll
            for (int ks = 0; ks < 4; ks++) {
                u32 a0 = sP[rq * 36 + ks * 8 + t4];
                u32 a1 = sP[(rq + 8) * 36 + ks * 8 + t4];
                u32 a2 = sP[rq * 36 + ks * 8 + t4 + 4];
                u32 a3 = sP[(rq + 8) * 36 + ks * 8 + t4 + 4];
                int vr0 = VOFF + (ks * 8 + t4) * 72;
                int vr1 = VOFF + (ks * 8 + t4 + 4) * 72;
#pragma unroll
                for (int nb = 0; nb < 2; nb++) {
                    u32 b0 = sC[vr0 + h * 16 + nb * 8 + g];
                    u32 b1 = sC[vr1 + h * 16 + nb * 8 + g];
                    mma16(O[h][nb], a0, a1, a2, a3, b0, b1);
                }
            }
            __syncwarp();   // before next head overwrites sP
        }
    }

    // reduce l across quad
#pragma unroll
    for (int h = 0; h < HH; h++) {
        lx[h] += __shfl_xor_sync(0xffffffffu, lx[h], 1);
        lx[h] += __shfl_xor_sync(0xffffffffu, lx[h], 2);
        lz[h] += __shfl_xor_sync(0xffffffffu, lz[h], 1);
        lz[h] += __shfl_xor_sync(0xffffffffu, lz[h], 2);
    }
    // normalized O -> sP, packed along d: col h*16+nb*8+2t4 -> kpair h*8+nb*4+t4
#pragma unroll
    for (int h = 0; h < HH; h++) {
        float ix = 1.f / lx[h], iz = 1.f / lz[h];
#pragma unroll
        for (int nb = 0; nb < 2; nb++) {
            int kp = h * 8 + nb * 4 + t4;
            sP[rq * 36 + kp] = bfp(O[h][nb].x * ix, O[h][nb].y * ix);
            sP[(rq + 8) * 36 + kp] = bfp(O[h][nb].z * iz, O[h][nb].w * iz);
        }
    }
    __syncthreads();
    // stage Wo as bf16 d-pairs into sC[0]
#pragma unroll
    for (int j = 0; j < 8; j++) {
        int idx = t + j * 256;
        int kp = idx >> 6, c = idx & 63;
        sC[kp * 72 + c] = bfp(Wo[(2 * kp) * DD + c], Wo[(2 * kp + 1) * DD + c]);
    }
    __syncthreads();

    // C2 = O @ Wo  (4 k16 steps)
    float4 C2[8];
#pragma unroll
    for (int nb = 0; nb < 8; nb++) C2[nb] = make_float4(0.f, 0.f, 0.f, 0.f);
#pragma unroll
    for (int ks = 0; ks < 4; ks++) {
        u32 a0 = sP[rq * 36 + ks * 8 + t4];
        u32 a1 = sP[(rq + 8) * 36 + ks * 8 + t4];
        u32 a2 = sP[rq * 36 + ks * 8 + t4 + 4];
        u32 a3 = sP[(rq + 8) * 36 + ks * 8 + t4 + 4];
        int wr0 = (ks * 8 + t4) * 72;
        int wr1 = (ks * 8 + t4 + 4) * 72;
#pragma unroll
        for (int nb = 0; nb < 8; nb++) {
            u32 b0 = sC[wr0 + nb * 8 + g];
            u32 b1 = sC[wr1 + nb * 8 + g];
            mma16(C2[nb], a0, a1, a2, a3, b0, b1);
        }
    }

    // Epilogue: +bo, +residual x (fp32), LayerNorm, store to g_x (in place)
#pragma unroll 1
    for (int rp = 0; rp < 2; rp++) {
        int r = rp ? rg8 : rg;
        bool vr = rp ? vg8 : vg;
        float vx[8], vy[8];
#pragma unroll
        for (int nb = 0; nb < 8; nb++) {
            int col = nb * 8 + 2 * t4;
            float2 xv = vr ? *(const float2*)&xbase[(size_t)r * DD + col]
                           : make_float2(0.f, 0.f);
            float cva = rp ? C2[nb].z : C2[nb].x;
            float cvb = rp ? C2[nb].w : C2[nb].y;
            vx[nb] = cva + sBo[col] + xv.x;
            vy[nb] = cvb + sBo[col + 1] + xv.y;
        }
        float s = 0.f;
#pragma unroll
        for (int nb = 0; nb < 8; nb++) s += vx[nb] + vy[nb];
        s += __shfl_xor_sync(0xffffffffu, s, 1);
        s += __shfl_xor_sync(0xffffffffu, s, 2);
        float m = s * (1.f / DD);
        float q = 0.f;
#pragma unroll
        for (int nb = 0; nb < 8; nb++) {
            float d0 = vx[nb] - m, d1 = vy[nb] - m;
            q += d0 * d0 + d1 * d1;
        }
        q += __shfl_xor_sync(0xffffffffu, q, 1);
        q += __shfl_xor_sync(0xffffffffu, q, 2);
        float inv = rsqrtf(q * (1.f / DD) + 1e-5f);
        if (vr) {
            float* op = g_x + ((size_t)b * NN + r) * DD;
#pragma unroll
            for (int nb = 0; nb < 8; nb++) {
                int col = nb * 8 + 2 * t4;
                float2 o2;
                o2.x = (vx[nb] - m) * inv * sG[col] + sBe[col];
                o2.y = (vy[nb] - m) * inv * sG[col + 1] + sBe[col + 1];
                *(float2*)&op[col] = o2;
            }
        }
    }
}

// ---------------------------------------------------------------------------
// Fused FFN with bf16 mma.sync.m16n8k16 (unchanged from R16).
__global__ __launch_bounds__(256, 2) void ffn_mma_kernel(const float* __restrict__ W1,
                                                         const float* __restrict__ b1,
                                                         const float* __restrict__ W2,
                                                         const float* __restrict__ b2,
                                                         const float* __restrict__ g2,
                                                         const float* __restrict__ be2,
                                                         float* __restrict__ xout) {
    extern __shared__ u32 smu[];
    u32* sX = smu;                        // [128][36] bf16x2
    u32* sH = sX + 128 * 36;              // [128][36] bf16x2
    u32* sW1u = sH + 128 * 36;            // [32 kpair][72] bf16x2
    u32* sW2u = sW1u + 32 * 72;           // [32 kpair][72] bf16x2
    float* sB1 = (float*)(sW2u + 32 * 72);
    float* sB2 = sB1 + 256;
    float* sG = sB2 + 64;
    float* sBe = sG + 64;

    int b = blockIdx.y, t = threadIdx.x;
    int w = t >> 5, L = t & 31, g = L >> 2, t4 = L & 3;
    int row0 = blockIdx.x * 128;

    if (t < 64) *(float4*)&sB1[t * 4] = *(const float4*)&b1[t * 4];
    if (t < 16) {
        *(float4*)&sB2[t * 4] = *(const float4*)&b2[t * 4];
        *(float4*)&sG[t * 4] = *(const float4*)&g2[t * 4];
        *(float4*)&sBe[t * 4] = *(const float4*)&be2[t * 4];
    }

    const float* xbase = g_x + (size_t)b * NN * DD;
    int rg = row0 + w * 16 + g;
    int rg8 = rg + 8;
    bool vg = rg < NN, vg8 = rg8 < NN;
    int rq = w * 16 + g;

    // stage X [128 rows][64 d] -> bf16 pairs, rows beyond NN zeroed
#pragma unroll
    for (int j = 0; j < 8; j++) {
        int idx = t + j * 256;
        int r = idx >> 4, c4 = idx & 15;
        int nr = row0 + r;
        uint2 u;
        if (nr < NN) {
            float4 v = *(const float4*)&xbase[(size_t)nr * DD + c4 * 4];
            u = make_uint2(bfp(v.x, v.y), bfp(v.z, v.w));
        } else u = make_uint2(0u, 0u);
        *(uint2*)&sX[r * 36 + c4 * 2] = u;
    }

    float4 C2[8];
#pragma unroll
    for (int nb = 0; nb < 8; nb++) C2[nb] = make_float4(0.f, 0.f, 0.f, 0.f);

#pragma unroll 1
    for (int fc = 0; fc < 4; fc++) {
        int f0 = fc * 64;
        __syncthreads();
#pragma unroll
        for (int j = 0; j < 8; j++) {
            int idx = t + j * 256;
            int kp = idx >> 6, c = idx & 63;
            float lo1 = W1[(2 * kp) * FF + f0 + c];
            float hi1 = W1[(2 * kp + 1) * FF + f0 + c];
            sW1u[kp * 72 + c] = bfp(lo1, hi1);
            float lo2 = W2[(size_t)(f0 + 2 * kp) * DD + c];
            float hi2 = W2[(size_t)(f0 + 2 * kp + 1) * DD + c];
            sW2u[kp * 72 + c] = bfp(lo2, hi2);
        }
        __syncthreads();

        float4 C1[8];
#pragma unroll
        for (int nb = 0; nb < 8; nb++) {
            int col = f0 + nb * 8 + 2 * t4;
            C1[nb] = make_float4(sB1[col], sB1[col + 1], sB1[col], sB1[col + 1]);
        }
#pragma unroll
        for (int ks = 0; ks < 4; ks++) {
            u32 a0 = sX[rq * 36 + ks * 8 + t4];
            u32 a1 = sX[(rq + 8) * 36 + ks * 8 + t4];
            u32 a2 = sX[rq * 36 + ks * 8 + t4 + 4];
            u32 a3 = sX[(rq + 8) * 36 + ks * 8 + t4 + 4];
            int wr0 = (ks * 8 + t4) * 72;
            int wr1 = (ks * 8 + t4 + 4) * 72;
#pragma unroll
            for (int nb = 0; nb < 8; nb++) {
                u32 b0 = sW1u[wr0 + nb * 8 + g];
                u32 b1r = sW1u[wr1 + nb * 8 + g];
                mma16(C1[nb], a0, a1, a2, a3, b0, b1r);
            }
        }
#pragma unroll
        for (int nb = 0; nb < 8; nb++) {
            float h0 = C1[nb].x, h1 = C1[nb].y, h2 = C1[nb].z, h3 = C1[nb].w;
            h0 = 0.5f * h0 * (1.f + erff(h0 * 0.70710678118654752440f));
            h1 = 0.5f * h1 * (1.f + erff(h1 * 0.70710678118654752440f));
            h2 = 0.5f * h2 * (1.f + erff(h2 * 0.70710678118654752440f));
            h3 = 0.5f * h3 * (1.f + erff(h3 * 0.70710678118654752440f));
            int kp = nb * 4 + t4;
            sH[rq * 36 + kp] = bfp(h0, h1);
            sH[(rq + 8) * 36 + kp] = bfp(h2, h3);
        }
        __syncwarp();
#pragma unroll
        for (int ks = 0; ks < 4; ks++) {
            u32 a0 = sH[rq * 36 + ks * 8 + t4];
            u32 a1 = sH[(rq + 8) * 36 + ks * 8 + t4];
            u32 a2 = sH[rq * 36 + ks * 8 + t4 + 4];
            u32 a3 = sH[(rq + 8) * 36 + ks * 8 + t4 + 4];
            int wr0 = (ks * 8 + t4) * 72;
            int wr1 = (ks * 8 + t4 + 4) * 72;
#pragma unroll
            for (int nb = 0; nb < 8; nb++) {
                u32 b0 = sW2u[wr0 + nb * 8 + g];
                u32 b1r = sW2u[wr1 + nb * 8 + g];
                mma16(C2[nb], a0, a1, a2, a3, b0, b1r);
            }
        }
        __syncwarp();
    }

    // Epilogue: +b2, +residual x (fp32 from gmem), LayerNorm, store.
#pragma unroll 1
    for (int rp = 0; rp < 2; rp++) {
        int r = rp ? rg8 : rg;
        bool vr = rp ? vg8 : vg;
        float vx[8], vy[8];
#pragma unroll
        for (int nb = 0; nb < 8; nb++) {
            int col = nb * 8 + 2 * t4;
            float2 xv = vr ? *(const float2*)&xbase[(size_t)r * DD + col]
                           : make_float2(0.f, 0.f);
            float cva = rp ? C2[nb].z : C2[nb].x;
            float cvb = rp ? C2[nb].w : C2[nb].y;
            vx[nb] = cva + sB2[col] + xv.x;
            vy[nb] = cvb + sB2[col + 1] + xv.y;
        }
        float s = 0.f;
#pragma unroll
        for (int nb = 0; nb < 8; nb++) s += vx[nb] + vy[nb];
        s += __shfl_xor_sync(0xffffffffu, s, 1);
        s += __shfl_xor_sync(0xffffffffu, s, 2);
        float m = s * (1.f / DD);
        float q = 0.f;
#pragma unroll
        for (int nb = 0; nb < 8; nb++) {
            float d0 = vx[nb] - m, d1 = vy[nb] - m;
            q += d0 * d0 + d1 * d1;
        }
        q += __shfl_xor_sync(0xffffffffu, q, 1);
        q += __shfl_xor_sync(0xffffffffu, q, 2);
        float inv = rsqrtf(q * (1.f / DD) + 1e-5f);
        if (vr) {
            float* op = xout + ((size_t)b * NN + r) * DD;
#pragma unroll
            for (int nb = 0; nb < 8; nb++) {
                int col = nb * 8 + 2 * t4;
                float2 o2;
                o2.x = (vx[nb] - m) * inv * sG[col] + sBe[col];
                o2.y = (vy[nb] - m) * inv * sG[col + 1] + sBe[col + 1];
                *(float2*)&op[col] = o2;
            }
        }
    }
}

// ---------------------------------------------------------------------------
extern "C" void kernel_launch(void* const* d_in, const int* in_sizes, int n_in,
                              void* d_out, int out_size) {
    const float* expr = (const float*)d_in[0];
    const float* emb = (const float*)d_in[1];
    const float* Wq = (const float*)d_in[2];
    const float* Wk = (const float*)d_in[3];
    const float* Wv = (const float*)d_in[4];
    const float* projK = (const float*)d_in[5];
    const float* projV = (const float*)d_in[6];
    const float* Wo = (const float*)d_in[7];
    const float* bo = (const float*)d_in[8];
    const float* g1 = (const float*)d_in[9];
    const float* be1 = (const float*)d_in[10];
    const float* W1 = (const float*)d_in[11];
    const float* bf1 = (const float*)d_in[12];
    const float* W2 = (const float*)d_in[13];
    const float* bf2 = (const float*)d_in[14];
    const float* g2 = (const float*)d_in[15];
    const float* be2 = (const float*)d_in[16];
    float* out = (float*)d_out;

    void* xaddr = nullptr;
    cudaGetSymbolAddress(&xaddr, g_x);
    float* gx = (float*)xaddr;

    cudaFuncSetAttribute(attn_mma_kernel, cudaFuncAttributeMaxDynamicSharedMemorySize,
                         ATTN_SMEM_BYTES);
    cudaFuncSetAttribute(ffn_mma_kernel, cudaFuncAttributeMaxDynamicSharedMemorySize,
                         FFN_SMEM_BYTES);

    embed_kernel<<<(BB * NN + 255) / 256, 256>>>(expr, emb);

    for (int l = 0; l < LLAYERS; l++) {
        proj_mma_kernel<<<dim3(NSPLIT, BB, 2), 256>>>(projK + (size_t)l * NN * KK,
                                                      projV + (size_t)l * NN * KK);
        reduce_kernel<<<(2 * BB * KK * DD) / 256, 256>>>();
        kvproj_kernel<<<dim3(KK / 4, BB, 2), 256>>>(Wk + l * DD * DD,
                                                    Wv + l * DD * DD);
        attn_mma_kernel<<<dim3(ATILES, BB), 256, ATTN_SMEM_BYTES>>>(
            Wq + l * DD * DD, Wo + l * DD * DD, bo + l * DD, g1 + l * DD,
            be1 + l * DD);
        ffn_mma_kernel<<<dim3(ATILES, BB), 256, FFN_SMEM_BYTES>>>(
            W1 + (size_t)l * DD * FF, bf1 + l * FF, W2 + (size_t)l * FF * DD,
            bf2 + l * DD, g2 + l * DD, be2 + l * DD,
            (l == LLAYERS - 1) ? out : gx);
    }
}